// round 15
// baseline (speedup 1.0000x reference)
#include <cuda_runtime.h>
#include <cuda_fp16.h>
#include <cstdint>

#define BB 4
#define NN 4096
#define C1 320
#define C2 256
#define HH 5
#define HD 64
#define MTOT (BB*NN)

// ---------------- scratch (device globals; no allocation allowed) ----------
__device__ __align__(16) __half g_x1h[MTOT*C1];
__device__ __align__(16) __half g_x2h[MTOT*C2];
__device__ __align__(16) __half g_wcat1[3*C1*C1];   // [wq1 ; wkv2], K=C1
__device__ __align__(16) __half g_wcat2[3*C1*C2];   // [wq2 ; wkv1], K=C2
__device__ __align__(16) __half g_wp1[C1*C1];
__device__ __align__(16) __half g_wp2[C1*C1];
// Q: [B,H,N,HD] per-head planes, SW128-swizzled within each 128B row
__device__ __align__(1024) __half g_q1[(size_t)MTOT*C1];
__device__ __align__(1024) __half g_q2[(size_t)MTOT*C1];
// KV: [B,H,2,N,HD] planes, swizzled
__device__ __align__(1024) __half g_kv1[(size_t)MTOT*2*C1];
__device__ __align__(1024) __half g_kv2[(size_t)MTOT*2*C1];
__device__ __align__(16) __half g_y1[(size_t)MTOT*C1];
__device__ __align__(16) __half g_y2[(size_t)MTOT*C1];

// ---------------- helpers ---------------------------------------------------
__device__ __forceinline__ uint32_t smem_u32(const void* p) {
    return (uint32_t)__cvta_generic_to_shared(p);
}
__device__ __forceinline__ void cp_async16(uint32_t dst, const void* src) {
    asm volatile("cp.async.cg.shared.global [%0], [%1], 16;\n" :: "r"(dst), "l"(src));
}
__device__ __forceinline__ void cp_commit() {
    asm volatile("cp.async.commit_group;\n" ::: "memory");
}
__device__ __forceinline__ void cp_wait1() {
    asm volatile("cp.async.wait_group 1;\n" ::: "memory");
}
__device__ __forceinline__ void bulk_cp(uint32_t dst, const void* src, uint32_t bytes, uint32_t mbar) {
    asm volatile("cp.async.bulk.shared::cluster.global.mbarrier::complete_tx::bytes [%0], [%1], %2, [%3];"
                 :: "r"(dst), "l"(src), "r"(bytes), "r"(mbar) : "memory");
}
__device__ __forceinline__ void mbar_init(uint32_t mbar, uint32_t cnt) {
    asm volatile("mbarrier.init.shared.b64 [%0], %1;" :: "r"(mbar), "r"(cnt) : "memory");
}
__device__ __forceinline__ void mbar_expect(uint32_t mbar, uint32_t bytes) {
    asm volatile("mbarrier.arrive.expect_tx.shared.b64 _, [%0], %1;" :: "r"(mbar), "r"(bytes) : "memory");
}
__device__ __forceinline__ void mbar_arrive(uint32_t mbar) {
    asm volatile("mbarrier.arrive.shared.b64 _, [%0];" :: "r"(mbar) : "memory");
}
__device__ __forceinline__ void mbar_wait(uint32_t mbar, uint32_t parity) {
    asm volatile(
        "{\n\t.reg .pred P;\n\t"
        "WAIT_%=:\n\t"
        "mbarrier.try_wait.parity.acquire.cta.shared::cta.b64 P, [%0], %1, 0x989680;\n\t"
        "@P bra.uni DONE_%=;\n\t"
        "bra.uni WAIT_%=;\n\t"
        "DONE_%=:\n\t}"
        :: "r"(mbar), "r"(parity) : "memory");
}
__device__ __forceinline__ void ldm_x4(uint32_t& r0, uint32_t& r1, uint32_t& r2, uint32_t& r3, uint32_t addr) {
    asm volatile("ldmatrix.sync.aligned.m8n8.x4.shared.b16 {%0,%1,%2,%3}, [%4];"
                 : "=r"(r0), "=r"(r1), "=r"(r2), "=r"(r3) : "r"(addr));
}
__device__ __forceinline__ void ldm_x4_t(uint32_t& r0, uint32_t& r1, uint32_t& r2, uint32_t& r3, uint32_t addr) {
    asm volatile("ldmatrix.sync.aligned.m8n8.x4.trans.shared.b16 {%0,%1,%2,%3}, [%4];"
                 : "=r"(r0), "=r"(r1), "=r"(r2), "=r"(r3) : "r"(addr));
}
__device__ __forceinline__ void mma16816(float* c, const uint32_t* a, uint32_t b0, uint32_t b1) {
    asm volatile("mma.sync.aligned.m16n8k16.row.col.f32.f16.f16.f32 "
                 "{%0,%1,%2,%3}, {%4,%5,%6,%7}, {%8,%9}, {%0,%1,%2,%3};"
                 : "+f"(c[0]), "+f"(c[1]), "+f"(c[2]), "+f"(c[3])
                 : "r"(a[0]), "r"(a[1]), "r"(a[2]), "r"(a[3]), "r"(b0), "r"(b1));
}
// f16-accumulator HMMA: D packed as 2x half2 regs; 2x tensor rate.
__device__ __forceinline__ void mma16816h(uint32_t& d0, uint32_t& d1, const uint32_t* a, uint32_t b0, uint32_t b1) {
    asm volatile("mma.sync.aligned.m16n8k16.row.col.f16.f16.f16.f16 "
                 "{%0,%1}, {%2,%3,%4,%5}, {%6,%7}, {%0,%1};"
                 : "+r"(d0), "+r"(d1)
                 : "r"(a[0]), "r"(a[1]), "r"(a[2]), "r"(a[3]), "r"(b0), "r"(b1));
}
__device__ __forceinline__ uint32_t h2ex2(uint32_t x) {
    uint32_t y;
    asm("ex2.approx.f16x2 %0, %1;" : "=r"(y) : "r"(x));
    return y;
}
__device__ __forceinline__ __half2 u2h(uint32_t x) {
    return *reinterpret_cast<__half2*>(&x);
}

typedef __half row72[72];

// ---------------- merged fp32 -> fp16 conversion (one launch) ---------------
struct ConvArgs {
    const float4* src[8];
    uint2*        dst[8];
    float         scale[8];
    int           cum[9];   // prefix sums of n/4
};

__global__ void f2h_multi(ConvArgs a, int total4) {
    int i = blockIdx.x * blockDim.x + threadIdx.x;
    if (i >= total4) return;
    int seg = 0;
#pragma unroll
    for (int s = 0; s < 7; s++) seg += (i >= a.cum[s + 1]) ? 1 : 0;
    int j = i - a.cum[seg];
    float4 v = a.src[seg][j];
    float sc = a.scale[seg];
    __half2 h0 = __floats2half2_rn(v.x * sc, v.y * sc);
    __half2 h1 = __floats2half2_rn(v.z * sc, v.w * sc);
    a.dst[seg][j] = make_uint2(*(uint32_t*)&h0, *(uint32_t*)&h1);
}

// ---------------- QKV projection GEMM (both branches via blockIdx.z) ---------
// 128x64 block tile, 256 threads = 8 warps x 16-row tiles, 2-stage double
// buffer (55.3KB): low regs (~80) -> 3 blocks/SM = 24 warps/SM. Round-14
// profile showed 16 warps still latency-bound; occupancy is the lever.
__global__ __launch_bounds__(256, 3)
void gemm_qkv(const __half* __restrict__ A1, const __half* __restrict__ Bw1,
              __half* __restrict__ OutQ1, __half* __restrict__ OutKV1, int K1,
              const __half* __restrict__ A2, const __half* __restrict__ Bw2,
              __half* __restrict__ OutQ2, __half* __restrict__ OutKV2, int K2)
{
    extern __shared__ __align__(16) char smem_raw[];
    row72* As = (row72*)smem_raw;                    // [2*128] rows
    row72* Bs = (row72*)(smem_raw + 2*128*72*2);     // [2*64] rows

    const int tid = threadIdx.x, lane = tid & 31, w = tid >> 5;
    const int m0 = blockIdx.y * 128;
    const int n0 = blockIdx.x * 64;
    const bool z = blockIdx.z != 0;
    const __half* A  = z ? A2  : A1;
    const __half* Bw = z ? Bw2 : Bw1;
    __half* OutQ  = z ? OutQ2  : OutQ1;
    __half* OutKV = z ? OutKV2 : OutKV1;
    const int K = z ? K2 : K1;

    auto load_stage = [&](int kt, int st) {
#pragma unroll
        for (int it = 0; it < 4; it++) {
            int l = it * 256 + tid;
            int r = l >> 3, c = (l & 7) * 8;
            cp_async16(smem_u32(&As[st*128 + r][c]), &A[(size_t)(m0 + r) * K + kt + c]);
        }
#pragma unroll
        for (int it = 0; it < 2; it++) {
            int l = it * 256 + tid;
            int r = l >> 3, c = (l & 7) * 8;
            cp_async16(smem_u32(&Bs[st*64 + r][c]), &Bw[(size_t)(n0 + r) * K + kt + c]);
        }
        cp_commit();
    };

    float acc[8][4];
#pragma unroll
    for (int j = 0; j < 8; j++)
#pragma unroll
        for (int x = 0; x < 4; x++) acc[j][x] = 0.f;

    const int nk = K / 64;              // 4 or 5
    load_stage(0, 0);
    load_stage(64, 1);
    const int brow = ((lane >> 4) << 3) + (lane & 7);
    const int bcol = ((lane >> 3) & 1) * 8;

    for (int t = 0; t < nk; t++) {
        cp_wait1();
        __syncthreads();
        const int st = t & 1;
        const uint32_t a_base = smem_u32(&As[st*128 + 16*w + (lane & 15)][8 * (lane >> 4)]);
#pragma unroll
        for (int ks = 0; ks < 4; ks++) {
            uint32_t a[4];
            ldm_x4(a[0], a[1], a[2], a[3], a_base + ks * 32);
#pragma unroll
            for (int jp = 0; jp < 4; jp++) {
                uint32_t b0, b1, b2, b3;
                ldm_x4(b0, b1, b2, b3, smem_u32(&Bs[st*64 + 16*jp + brow][ks*16 + bcol]));
                mma16816(acc[2*jp],     a, b0, b1);
                mma16816(acc[2*jp + 1], a, b2, b3);
            }
        }
        __syncthreads();                // all reads of buffer st done
        if (t + 2 < nk) load_stage((t + 2) * 64, st);
    }

    // epilogue: scatter into swizzled per-head plane
    const int r0 = m0 + 16*w + (lane >> 2);
    const int bb = r0 >> 12;
    const int na = r0 & (NN - 1);
    size_t plane;
    char* base;
    if (n0 < C1) {
        plane = (size_t)bb * HH + (n0 >> 6);
        base = (char*)OutQ + plane * ((size_t)NN * 128);
    } else {
        int c = n0 - C1;
        plane = ((size_t)bb * HH + ((c % C1) >> 6)) * 2 + (c / C1);
        base = (char*)OutKV + plane * ((size_t)NN * 128);
    }
    const int dxor = (na & 7) << 4;
    const int d2b = 4 * (lane & 3);
#pragma unroll
    for (int j = 0; j < 8; j++) {
        int db = d2b + 16 * j;
        *(__half2*)(base + (size_t)na * 128 + (db ^ dxor))       = __floats2half2_rn(acc[j][0], acc[j][1]);
        *(__half2*)(base + (size_t)(na + 8) * 128 + (db ^ dxor)) = __floats2half2_rn(acc[j][2], acc[j][3]);
    }
}

// ---------------- output projection GEMM (both branches via blockIdx.z) ------
__global__ __launch_bounds__(256, 3)
void gemm_proj(const __half* __restrict__ Y1, const __half* __restrict__ Bw1,
               const __half* __restrict__ Y2, const __half* __restrict__ Bw2,
               float* __restrict__ out,
               const float* __restrict__ b1, const float* __restrict__ b2)
{
    extern __shared__ __align__(16) char smem_raw[];
    row72* As = (row72*)smem_raw;
    row72* Bs = (row72*)(smem_raw + 2*128*72*2);

    const int tid = threadIdx.x, lane = tid & 31, w = tid >> 5;
    const int m0 = blockIdx.y * 128;
    const int n0 = blockIdx.x * 64;
    const bool z = blockIdx.z != 0;
    const __half* A  = z ? Y2  : Y1;
    const __half* Bw = z ? Bw2 : Bw1;
    const float* bias = z ? b2 : b1;
    const int coff = z ? C1 : 0;
    const int K = C1;

    auto load_stage = [&](int kt, int st) {
#pragma unroll
        for (int it = 0; it < 4; it++) {
            int l = it * 256 + tid;
            int r = l >> 3, c = (l & 7) * 8;
            cp_async16(smem_u32(&As[st*128 + r][c]), &A[(size_t)(m0 + r) * K + kt + c]);
        }
#pragma unroll
        for (int it = 0; it < 2; it++) {
            int l = it * 256 + tid;
            int r = l >> 3, c = (l & 7) * 8;
            cp_async16(smem_u32(&Bs[st*64 + r][c]), &Bw[(size_t)(n0 + r) * K + kt + c]);
        }
        cp_commit();
    };

    float acc[8][4];
#pragma unroll
    for (int j = 0; j < 8; j++)
#pragma unroll
        for (int x = 0; x < 4; x++) acc[j][x] = 0.f;

    const int nk = K / 64;              // 5
    load_stage(0, 0);
    load_stage(64, 1);
    const int brow = ((lane >> 4) << 3) + (lane & 7);
    const int bcol = ((lane >> 3) & 1) * 8;

    for (int t = 0; t < nk; t++) {
        cp_wait1();
        __syncthreads();
        const int st = t & 1;
        const uint32_t a_base = smem_u32(&As[st*128 + 16*w + (lane & 15)][8 * (lane >> 4)]);
#pragma unroll
        for (int ks = 0; ks < 4; ks++) {
            uint32_t a[4];
            ldm_x4(a[0], a[1], a[2], a[3], a_base + ks * 32);
#pragma unroll
            for (int jp = 0; jp < 4; jp++) {
                uint32_t b0, b1r, b2, b3;
                ldm_x4(b0, b1r, b2, b3, smem_u32(&Bs[st*64 + 16*jp + brow][ks*16 + bcol]));
                mma16816(acc[2*jp],     a, b0, b1r);
                mma16816(acc[2*jp + 1], a, b2, b3);
            }
        }
        __syncthreads();
        if (t + 2 < nk) load_stage((t + 2) * 64, st);
    }

    const int r0 = m0 + 16*w + (lane >> 2);
    const int cb = n0 + 2 * (lane & 3);
#pragma unroll
    for (int j = 0; j < 8; j++) {
        int c = cb + 8*j;
        float bv0 = bias[c], bv1 = bias[c + 1];
        out[(size_t)r0 * (2*C1) + coff + c]           = acc[j][0] + bv0;
        out[(size_t)r0 * (2*C1) + coff + c + 1]       = acc[j][1] + bv1;
        out[(size_t)(r0 + 8) * (2*C1) + coff + c]     = acc[j][2] + bv0;
        out[(size_t)(r0 + 8) * (2*C1) + coff + c + 1] = acc[j][3] + bv1;
    }
}

// ---------------- flash attention ---------------------------------------------
// 3-stage ring of 128-key stages, rotating producer, 16-row warps, 2 blocks/SM.
// NEW: odd warps process the two 64-key sub-tiles in reverse order, decorrelating
// the per-warp QK->ex2->PV phases so the tensor pipe stays fed while other warps
// run softmax (zero register cost; commutative accumulation, order-only change).
#define FA_OFF_Q   0                      // 128 rows x 128B = 16384
#define FA_OFF_KV  16384                  // stage s: K at +s*32768, V at +16384
#define FA_OFF_MB  114688                 // q(8) full[3](24) empty[3](24)
#define FA_SMEM    114752

__global__ __launch_bounds__(256, 2)
void flash_attn(const __half* __restrict__ Q1, const __half* __restrict__ KV1, __half* __restrict__ Y1,
                const __half* __restrict__ Q2, const __half* __restrict__ KV2, __half* __restrict__ Y2)
{
    extern __shared__ __align__(1024) char smem_raw[];
    const uint32_t sb = smem_u32(smem_raw);
    const uint32_t mbq = sb + FA_OFF_MB;
    const uint32_t mbf = mbq + 8;    // full[0..2]
    const uint32_t mbe = mbq + 32;   // empty[0..2]

    const int tid = threadIdx.x, lane = tid & 31, w = tid >> 5;
    const int q0 = blockIdx.x * 128;
    const int b = blockIdx.y / HH, h = blockIdx.y % HH;
    const bool br = blockIdx.z != 0;

    const __half* Q  = br ? Q2  : Q1;
    const __half* KV = br ? KV2 : KV1;
    __half*       Y  = br ? Y2  : Y1;

    const char* qplane = (const char*)Q  + ((size_t)b * HH + h) * ((size_t)NN * 128);
    const char* kplane = (const char*)KV + (((size_t)b * HH + h) * 2) * ((size_t)NN * 128);
    const char* vplane = kplane + (size_t)NN * 128;
    __half* Yb = Y + (size_t)b * NN * C1 + h * HD;

    const int nk2 = NN / 128;            // 32 stages of 128 keys

    if (tid == 0) {
        mbar_init(mbq, 1);
#pragma unroll
        for (int s = 0; s < 3; s++) {
            mbar_init(mbf + 8*s, 1);
            mbar_init(mbe + 8*s, 8);   // one arrival per warp
        }
    }
    __syncthreads();
    if (tid == 0) {
        mbar_expect(mbq, 16384);
        bulk_cp(sb + FA_OFF_Q, qplane + (size_t)q0 * 128, 16384, mbq);
#pragma unroll
        for (int s = 0; s < 3; s++) {
            mbar_expect(mbf + 8*s, 32768);
            bulk_cp(sb + FA_OFF_KV + s*32768,         kplane + (size_t)s * 16384, 16384, mbf + 8*s);
            bulk_cp(sb + FA_OFF_KV + s*32768 + 16384, vplane + (size_t)s * 16384, 16384, mbf + 8*s);
        }
    }

    // lane-constant swizzle XOR (row&7 == lane&7 for all fragment addresses)
    const int sxor = (lane & 7) << 4;

    // wait Q, pull persistent A fragments
    mbar_wait(mbq, 0);
    uint32_t aq[4][4];
    {
        const int qrow = 16*w + (lane & 15);
        const uint32_t qbase = sb + FA_OFF_Q + qrow * 128;
        const int qc = 16 * (lane >> 4);
#pragma unroll
        for (int ks = 0; ks < 4; ks++)
            ldm_x4(aq[ks][0], aq[ks][1], aq[ks][2], aq[ks][3], qbase + ((ks*32 + qc) ^ sxor));
    }

    float O[8][4];
#pragma unroll
    for (int j = 0; j < 8; j++)
#pragma unroll
        for (int x = 0; x < 4; x++) O[j][x] = 0.f;
    float lacc[2] = {0.f, 0.f};
    const __half2 hzero = __floats2half2_rn(0.f, 0.f);

    const int krow = ((lane >> 4) << 3) + (lane & 7);
    const int kc = 16 * ((lane >> 3) & 1);
    const int vrow = (((lane >> 3) & 1) << 3) + (lane & 7);
    const int vc = 16 * (lane >> 4);
    const int wpar = w & 1;              // sub-tile order stagger

    int st = 0, ph = 0;
    for (int kt = 0; kt < nk2; kt++) {
        mbar_wait(mbf + 8*st, ph);
        const uint32_t stage = sb + FA_OFF_KV + st * 32768;

#pragma unroll
        for (int subi = 0; subi < 2; subi++) {
            const int sub = subi ^ wpar;   // even warps: 0,1; odd warps: 1,0
            const uint32_t kbase = stage + sub * 8192;
            const uint32_t vbase = stage + 16384 + sub * 8192;

            // S = Q K^T, f16 accum
            uint32_t su[8][2];
#pragma unroll
            for (int n = 0; n < 8; n++) { su[n][0] = 0; su[n][1] = 0; }
#pragma unroll
            for (int ks = 0; ks < 4; ks++) {
#pragma unroll
                for (int jp = 0; jp < 4; jp++) {
                    uint32_t b0, b1, b2, b3;
                    ldm_x4(b0, b1, b2, b3, kbase + (16*jp + krow) * 128 + ((ks*32 + kc) ^ sxor));
                    mma16816h(su[2*jp][0],     su[2*jp][1],     aq[ks], b0, b1);
                    mma16816h(su[2*jp + 1][0], su[2*jp + 1][1], aq[ks], b2, b3);
                }
            }

            // p = 2^s in place, interleaved with PV mmas; l in half2 per subtile
            __half2 lh0 = hzero, lh1 = hzero;
#pragma unroll
            for (int ks = 0; ks < 4; ks++) {
                uint32_t pa[4];
                pa[0] = h2ex2(su[2*ks][0]);
                pa[1] = h2ex2(su[2*ks][1]);
                pa[2] = h2ex2(su[2*ks + 1][0]);
                pa[3] = h2ex2(su[2*ks + 1][1]);
                lh0 = __hadd2(lh0, __hadd2(u2h(pa[0]), u2h(pa[2])));
                lh1 = __hadd2(lh1, __hadd2(u2h(pa[1]), u2h(pa[3])));
#pragma unroll
                for (int dp = 0; dp < 4; dp++) {
                    uint32_t b0, b1, b2, b3;
                    ldm_x4_t(b0, b1, b2, b3, vbase + (ks*16 + vrow) * 128 + ((dp*32 + vc) ^ sxor));
                    mma16816(O[2*dp],     pa, b0, b1);
                    mma16816(O[2*dp + 1], pa, b2, b3);
                }
            }
            {
                float2 f0 = __half22float2(lh0);
                float2 f1 = __half22float2(lh1);
                lacc[0] += f0.x + f0.y;
                lacc[1] += f1.x + f1.y;
            }
        }

        // consumer release: this warp is done reading stage st
        if (lane == 0) mbar_arrive(mbe + 8*st);

        // rotating producer: warp (kt&7) refills stage st with tile kt+3
        if (w == (kt & 7) && lane == 0 && kt + 3 < nk2) {
            mbar_wait(mbe + 8*st, ph);
            mbar_expect(mbf + 8*st, 32768);
            bulk_cp(stage,         kplane + (size_t)(kt + 3) * 16384, 16384, mbf + 8*st);
            bulk_cp(stage + 16384, vplane + (size_t)(kt + 3) * 16384, 16384, mbf + 8*st);
        }

        if (++st == 3) { st = 0; ph ^= 1; }
    }

    // epilogue: reduce l across the 4 lanes of each row quad, scale, store
    float l0 = lacc[0], l1 = lacc[1];
    l0 += __shfl_xor_sync(0xffffffffu, l0, 1);
    l0 += __shfl_xor_sync(0xffffffffu, l0, 2);
    l1 += __shfl_xor_sync(0xffffffffu, l1, 1);
    l1 += __shfl_xor_sync(0xffffffffu, l1, 2);
    const float i0 = 1.f / l0, i1 = 1.f / l1;

    const int r0 = q0 + 16*w + (lane >> 2);
    const int cb = 2 * (lane & 3);
#pragma unroll
    for (int j = 0; j < 8; j++) {
        int c = cb + 8*j;
        *(__half2*)&Yb[(size_t)r0 * C1 + c]       = __floats2half2_rn(O[j][0] * i0, O[j][1] * i0);
        *(__half2*)&Yb[(size_t)(r0 + 8) * C1 + c] = __floats2half2_rn(O[j][2] * i1, O[j][3] * i1);
    }
}

// ---------------- launch ------------------------------------------------------
extern "C" void kernel_launch(void* const* d_in, const int* in_sizes, int n_in,
                              void* d_out, int out_size) {
    const float* x1  = (const float*)d_in[0];
    const float* x2  = (const float*)d_in[1];
    const float* q1w = (const float*)d_in[2];
    const float* q2w = (const float*)d_in[3];
    const float* kv1w = (const float*)d_in[4];
    const float* kv2w = (const float*)d_in[5];
    const float* p1w = (const float*)d_in[6];
    const float* p1b = (const float*)d_in[7];
    const float* p2w = (const float*)d_in[8];
    const float* p2b = (const float*)d_in[9];
    float* out = (float*)d_out;

    __half *x1h, *x2h, *wc1, *wc2, *wp1, *wp2, *q1, *q2, *kv1, *kv2, *y1, *y2;
    cudaGetSymbolAddress((void**)&x1h, g_x1h);
    cudaGetSymbolAddress((void**)&x2h, g_x2h);
    cudaGetSymbolAddress((void**)&wc1, g_wcat1);
    cudaGetSymbolAddress((void**)&wc2, g_wcat2);
    cudaGetSymbolAddress((void**)&wp1, g_wp1);
    cudaGetSymbolAddress((void**)&wp2, g_wp2);
    cudaGetSymbolAddress((void**)&q1, g_q1);
    cudaGetSymbolAddress((void**)&q2, g_q2);
    cudaGetSymbolAddress((void**)&kv1, g_kv1);
    cudaGetSymbolAddress((void**)&kv2, g_kv2);
    cudaGetSymbolAddress((void**)&y1, g_y1);
    cudaGetSymbolAddress((void**)&y2, g_y2);

    const int SMEM_G = 2 * (128 + 64) * 72 * 2;    // 55296 (2-stage, 3 blocks/SM @256thr)
    cudaFuncSetAttribute(flash_attn, cudaFuncAttributeMaxDynamicSharedMemorySize, FA_SMEM);
    cudaFuncSetAttribute(gemm_qkv,   cudaFuncAttributeMaxDynamicSharedMemorySize, SMEM_G);
    cudaFuncSetAttribute(gemm_proj,  cudaFuncAttributeMaxDynamicSharedMemorySize, SMEM_G);

    // fold HD^-0.5 AND log2(e) into q weights: S comes out in log2 units
    const float qscale = 0.125f * 1.44269504088896340736f;

    // merged conversion; q/kv weights land in concatenated buffers
    {
        ConvArgs a;
        const float* srcs[8] = {x1, x2, q1w, kv2w, q2w, kv1w, p1w, p2w};
        __half* dsts[8] = {x1h, x2h, wc1, wc1 + C1*C1, wc2, wc2 + C1*C2, wp1, wp2};
        int ns[8] = {MTOT*C1, MTOT*C2, C1*C1, 2*C1*C1, C1*C2, 2*C1*C2, C1*C1, C1*C1};
        float scs[8] = {1.f, 1.f, qscale, 1.f, qscale, 1.f, 1.f, 1.f};
        int cum = 0;
        for (int s = 0; s < 8; s++) {
            a.src[s] = (const float4*)srcs[s];
            a.dst[s] = (uint2*)dsts[s];
            a.scale[s] = scs[s];
            a.cum[s] = cum;
            cum += ns[s] / 4;
        }
        a.cum[8] = cum;
        f2h_multi<<<(cum + 255) / 256, 256>>>(a, cum);
    }

    // fused q+kv projections, both branches in one launch (z selects branch)
    gemm_qkv<<<dim3(3 * C1 / 64, MTOT / 128, 2), 256, SMEM_G>>>(
        x1h, wc1, q1, kv2, C1, x2h, wc2, q2, kv1, C2);

    // attention (both branches, one launch; 128 q-rows per block, 2 blocks/SM)
    flash_attn<<<dim3(NN / 128, BB * HH, 2), 256, FA_SMEM>>>(q1, kv1, y1, q2, kv2, y2);

    // output projections with bias (both branches), concat into out
    gemm_proj<<<dim3(C1 / 64, MTOT / 128, 2), 256, SMEM_G>>>(y1, wp1, y2, wp2, out, p1b, p2b);
}

// round 16
// speedup vs baseline: 1.0566x; 1.0566x over previous
#include <cuda_runtime.h>
#include <cuda_fp16.h>
#include <cstdint>

#define BB 4
#define NN 4096
#define C1 320
#define C2 256
#define HH 5
#define HD 64
#define MTOT (BB*NN)

// ---------------- scratch (device globals; no allocation allowed) ----------
__device__ __align__(16) __half g_x1h[MTOT*C1];
__device__ __align__(16) __half g_x2h[MTOT*C2];
__device__ __align__(16) __half g_wcat1[3*C1*C1];   // [wq1 ; wkv2], K=C1
__device__ __align__(16) __half g_wcat2[3*C1*C2];   // [wq2 ; wkv1], K=C2
__device__ __align__(16) __half g_wp1[C1*C1];
__device__ __align__(16) __half g_wp2[C1*C1];
// Q: [B,H,N,HD] per-head planes, SW128-swizzled within each 128B row
__device__ __align__(1024) __half g_q1[(size_t)MTOT*C1];
__device__ __align__(1024) __half g_q2[(size_t)MTOT*C1];
// KV: [B,H,2,N,HD] planes, swizzled
__device__ __align__(1024) __half g_kv1[(size_t)MTOT*2*C1];
__device__ __align__(1024) __half g_kv2[(size_t)MTOT*2*C1];
__device__ __align__(16) __half g_y1[(size_t)MTOT*C1];
__device__ __align__(16) __half g_y2[(size_t)MTOT*C1];

// ---------------- helpers ---------------------------------------------------
__device__ __forceinline__ uint32_t smem_u32(const void* p) {
    return (uint32_t)__cvta_generic_to_shared(p);
}
__device__ __forceinline__ void cp_async16(uint32_t dst, const void* src) {
    asm volatile("cp.async.cg.shared.global [%0], [%1], 16;\n" :: "r"(dst), "l"(src));
}
__device__ __forceinline__ void cp_commit() {
    asm volatile("cp.async.commit_group;\n" ::: "memory");
}
__device__ __forceinline__ void cp_wait1() {
    asm volatile("cp.async.wait_group 1;\n" ::: "memory");
}
__device__ __forceinline__ void bulk_cp(uint32_t dst, const void* src, uint32_t bytes, uint32_t mbar) {
    asm volatile("cp.async.bulk.shared::cluster.global.mbarrier::complete_tx::bytes [%0], [%1], %2, [%3];"
                 :: "r"(dst), "l"(src), "r"(bytes), "r"(mbar) : "memory");
}
__device__ __forceinline__ void mbar_init(uint32_t mbar, uint32_t cnt) {
    asm volatile("mbarrier.init.shared.b64 [%0], %1;" :: "r"(mbar), "r"(cnt) : "memory");
}
__device__ __forceinline__ void mbar_expect(uint32_t mbar, uint32_t bytes) {
    asm volatile("mbarrier.arrive.expect_tx.shared.b64 _, [%0], %1;" :: "r"(mbar), "r"(bytes) : "memory");
}
__device__ __forceinline__ void mbar_arrive(uint32_t mbar) {
    asm volatile("mbarrier.arrive.shared.b64 _, [%0];" :: "r"(mbar) : "memory");
}
__device__ __forceinline__ void mbar_wait(uint32_t mbar, uint32_t parity) {
    asm volatile(
        "{\n\t.reg .pred P;\n\t"
        "WAIT_%=:\n\t"
        "mbarrier.try_wait.parity.acquire.cta.shared::cta.b64 P, [%0], %1, 0x989680;\n\t"
        "@P bra.uni DONE_%=;\n\t"
        "bra.uni WAIT_%=;\n\t"
        "DONE_%=:\n\t}"
        :: "r"(mbar), "r"(parity) : "memory");
}
__device__ __forceinline__ void ldm_x4(uint32_t& r0, uint32_t& r1, uint32_t& r2, uint32_t& r3, uint32_t addr) {
    asm volatile("ldmatrix.sync.aligned.m8n8.x4.shared.b16 {%0,%1,%2,%3}, [%4];"
                 : "=r"(r0), "=r"(r1), "=r"(r2), "=r"(r3) : "r"(addr));
}
__device__ __forceinline__ void ldm_x4_t(uint32_t& r0, uint32_t& r1, uint32_t& r2, uint32_t& r3, uint32_t addr) {
    asm volatile("ldmatrix.sync.aligned.m8n8.x4.trans.shared.b16 {%0,%1,%2,%3}, [%4];"
                 : "=r"(r0), "=r"(r1), "=r"(r2), "=r"(r3) : "r"(addr));
}
__device__ __forceinline__ void mma16816(float* c, const uint32_t* a, uint32_t b0, uint32_t b1) {
    asm volatile("mma.sync.aligned.m16n8k16.row.col.f32.f16.f16.f32 "
                 "{%0,%1,%2,%3}, {%4,%5,%6,%7}, {%8,%9}, {%0,%1,%2,%3};"
                 : "+f"(c[0]), "+f"(c[1]), "+f"(c[2]), "+f"(c[3])
                 : "r"(a[0]), "r"(a[1]), "r"(a[2]), "r"(a[3]), "r"(b0), "r"(b1));
}
// f16-accumulator HMMA: D packed as 2x half2 regs; 2x tensor rate.
__device__ __forceinline__ void mma16816h(uint32_t& d0, uint32_t& d1, const uint32_t* a, uint32_t b0, uint32_t b1) {
    asm volatile("mma.sync.aligned.m16n8k16.row.col.f16.f16.f16.f16 "
                 "{%0,%1}, {%2,%3,%4,%5}, {%6,%7}, {%0,%1};"
                 : "+r"(d0), "+r"(d1)
                 : "r"(a[0]), "r"(a[1]), "r"(a[2]), "r"(a[3]), "r"(b0), "r"(b1));
}
__device__ __forceinline__ uint32_t h2ex2(uint32_t x) {
    uint32_t y;
    asm("ex2.approx.f16x2 %0, %1;" : "=r"(y) : "r"(x));
    return y;
}
__device__ __forceinline__ __half2 u2h(uint32_t x) {
    return *reinterpret_cast<__half2*>(&x);
}

typedef __half row72[72];

// ---------------- merged fp32 -> fp16 conversion (one launch) ---------------
struct ConvArgs {
    const float4* src[8];
    uint2*        dst[8];
    float         scale[8];
    int           cum[9];   // prefix sums of n/4
};

__global__ void f2h_multi(ConvArgs a, int total4) {
    int i = blockIdx.x * blockDim.x + threadIdx.x;
    if (i >= total4) return;
    int seg = 0;
#pragma unroll
    for (int s = 0; s < 7; s++) seg += (i >= a.cum[s + 1]) ? 1 : 0;
    int j = i - a.cum[seg];
    float4 v = a.src[seg][j];
    float sc = a.scale[seg];
    __half2 h0 = __floats2half2_rn(v.x * sc, v.y * sc);
    __half2 h1 = __floats2half2_rn(v.z * sc, v.w * sc);
    a.dst[seg][j] = make_uint2(*(uint32_t*)&h0, *(uint32_t*)&h1);
}

// ---------------- QKV projection GEMM (both branches via blockIdx.z) ---------
// 128x64 block tile, 128 threads = 4 warps x 32-row tiles, 2-stage double
// buffer (55.3KB) -> 4 blocks/SM (round-14 best config, restored).
__global__ __launch_bounds__(128, 4)
void gemm_qkv(const __half* __restrict__ A1, const __half* __restrict__ Bw1,
              __half* __restrict__ OutQ1, __half* __restrict__ OutKV1, int K1,
              const __half* __restrict__ A2, const __half* __restrict__ Bw2,
              __half* __restrict__ OutQ2, __half* __restrict__ OutKV2, int K2)
{
    extern __shared__ __align__(16) char smem_raw[];
    row72* As = (row72*)smem_raw;                    // [2*128] rows
    row72* Bs = (row72*)(smem_raw + 2*128*72*2);     // [2*64] rows

    const int tid = threadIdx.x, lane = tid & 31, w = tid >> 5;
    const int m0 = blockIdx.y * 128;
    const int n0 = blockIdx.x * 64;
    const bool z = blockIdx.z != 0;
    const __half* A  = z ? A2  : A1;
    const __half* Bw = z ? Bw2 : Bw1;
    __half* OutQ  = z ? OutQ2  : OutQ1;
    __half* OutKV = z ? OutKV2 : OutKV1;
    const int K = z ? K2 : K1;

    auto load_stage = [&](int kt, int st) {
#pragma unroll
        for (int it = 0; it < 8; it++) {
            int l = it * 128 + tid;
            int r = l >> 3, c = (l & 7) * 8;
            cp_async16(smem_u32(&As[st*128 + r][c]), &A[(size_t)(m0 + r) * K + kt + c]);
        }
#pragma unroll
        for (int it = 0; it < 4; it++) {
            int l = it * 128 + tid;
            int r = l >> 3, c = (l & 7) * 8;
            cp_async16(smem_u32(&Bs[st*64 + r][c]), &Bw[(size_t)(n0 + r) * K + kt + c]);
        }
        cp_commit();
    };

    float acc[2][8][4];
#pragma unroll
    for (int m = 0; m < 2; m++)
#pragma unroll
        for (int j = 0; j < 8; j++)
#pragma unroll
            for (int x = 0; x < 4; x++) acc[m][j][x] = 0.f;

    const int nk = K / 64;              // 4 or 5
    load_stage(0, 0);
    load_stage(64, 1);
    const int brow = ((lane >> 4) << 3) + (lane & 7);
    const int bcol = ((lane >> 3) & 1) * 8;

    for (int t = 0; t < nk; t++) {
        cp_wait1();
        __syncthreads();
        const int st = t & 1;
#pragma unroll
        for (int ks = 0; ks < 4; ks++) {
            uint32_t a[2][4];
#pragma unroll
            for (int m = 0; m < 2; m++)
                ldm_x4(a[m][0], a[m][1], a[m][2], a[m][3],
                       smem_u32(&As[st*128 + 32*w + 16*m + (lane & 15)][ks*16 + 8*(lane >> 4)]));
#pragma unroll
            for (int jp = 0; jp < 4; jp++) {
                uint32_t b0, b1, b2, b3;
                ldm_x4(b0, b1, b2, b3, smem_u32(&Bs[st*64 + 16*jp + brow][ks*16 + bcol]));
                mma16816(acc[0][2*jp],     a[0], b0, b1);
                mma16816(acc[0][2*jp + 1], a[0], b2, b3);
                mma16816(acc[1][2*jp],     a[1], b0, b1);
                mma16816(acc[1][2*jp + 1], a[1], b2, b3);
            }
        }
        __syncthreads();                        // all reads of buffer st done
        if (t + 2 < nk) load_stage((t + 2) * 64, st);
    }

    // epilogue: scatter into swizzled per-head plane
    const int d2b = 4 * (lane & 3);
#pragma unroll
    for (int m = 0; m < 2; m++) {
        const int r0 = m0 + 32*w + 16*m + (lane >> 2);
        const int bb = r0 >> 12;
        const int na = r0 & (NN - 1);
        size_t plane;
        char* base;
        if (n0 < C1) {
            plane = (size_t)bb * HH + (n0 >> 6);
            base = (char*)OutQ + plane * ((size_t)NN * 128);
        } else {
            int c = n0 - C1;
            plane = ((size_t)bb * HH + ((c % C1) >> 6)) * 2 + (c / C1);
            base = (char*)OutKV + plane * ((size_t)NN * 128);
        }
        const int dxor = (na & 7) << 4;
#pragma unroll
        for (int j = 0; j < 8; j++) {
            int db = d2b + 16 * j;
            *(__half2*)(base + (size_t)na * 128 + (db ^ dxor))       = __floats2half2_rn(acc[m][j][0], acc[m][j][1]);
            *(__half2*)(base + (size_t)(na + 8) * 128 + (db ^ dxor)) = __floats2half2_rn(acc[m][j][2], acc[m][j][3]);
        }
    }
}

// ---------------- output projection GEMM (both branches via blockIdx.z) ------
__global__ __launch_bounds__(128, 4)
void gemm_proj(const __half* __restrict__ Y1, const __half* __restrict__ Bw1,
               const __half* __restrict__ Y2, const __half* __restrict__ Bw2,
               float* __restrict__ out,
               const float* __restrict__ b1, const float* __restrict__ b2)
{
    extern __shared__ __align__(16) char smem_raw[];
    row72* As = (row72*)smem_raw;
    row72* Bs = (row72*)(smem_raw + 2*128*72*2);

    const int tid = threadIdx.x, lane = tid & 31, w = tid >> 5;
    const int m0 = blockIdx.y * 128;
    const int n0 = blockIdx.x * 64;
    const bool z = blockIdx.z != 0;
    const __half* A  = z ? Y2  : Y1;
    const __half* Bw = z ? Bw2 : Bw1;
    const float* bias = z ? b2 : b1;
    const int coff = z ? C1 : 0;
    const int K = C1;

    auto load_stage = [&](int kt, int st) {
#pragma unroll
        for (int it = 0; it < 8; it++) {
            int l = it * 128 + tid;
            int r = l >> 3, c = (l & 7) * 8;
            cp_async16(smem_u32(&As[st*128 + r][c]), &A[(size_t)(m0 + r) * K + kt + c]);
        }
#pragma unroll
        for (int it = 0; it < 4; it++) {
            int l = it * 128 + tid;
            int r = l >> 3, c = (l & 7) * 8;
            cp_async16(smem_u32(&Bs[st*64 + r][c]), &Bw[(size_t)(n0 + r) * K + kt + c]);
        }
        cp_commit();
    };

    float acc[2][8][4];
#pragma unroll
    for (int m = 0; m < 2; m++)
#pragma unroll
        for (int j = 0; j < 8; j++)
#pragma unroll
            for (int x = 0; x < 4; x++) acc[m][j][x] = 0.f;

    const int nk = K / 64;              // 5
    load_stage(0, 0);
    load_stage(64, 1);
    const int brow = ((lane >> 4) << 3) + (lane & 7);
    const int bcol = ((lane >> 3) & 1) * 8;

    for (int t = 0; t < nk; t++) {
        cp_wait1();
        __syncthreads();
        const int st = t & 1;
#pragma unroll
        for (int ks = 0; ks < 4; ks++) {
            uint32_t a[2][4];
#pragma unroll
            for (int m = 0; m < 2; m++)
                ldm_x4(a[m][0], a[m][1], a[m][2], a[m][3],
                       smem_u32(&As[st*128 + 32*w + 16*m + (lane & 15)][ks*16 + 8*(lane >> 4)]));
#pragma unroll
            for (int jp = 0; jp < 4; jp++) {
                uint32_t b0, b1r, b2, b3;
                ldm_x4(b0, b1r, b2, b3, smem_u32(&Bs[st*64 + 16*jp + brow][ks*16 + bcol]));
                mma16816(acc[0][2*jp],     a[0], b0, b1r);
                mma16816(acc[0][2*jp + 1], a[0], b2, b3);
                mma16816(acc[1][2*jp],     a[1], b0, b1r);
                mma16816(acc[1][2*jp + 1], a[1], b2, b3);
            }
        }
        __syncthreads();
        if (t + 2 < nk) load_stage((t + 2) * 64, st);
    }

    // epilogue: columns c, c+1 are adjacent -> pack as float2 stores
    const int cb = n0 + 2 * (lane & 3);
#pragma unroll
    for (int m = 0; m < 2; m++) {
        const int r0 = m0 + 32*w + 16*m + (lane >> 2);
#pragma unroll
        for (int j = 0; j < 8; j++) {
            int c = cb + 8*j;
            float bv0 = bias[c], bv1 = bias[c + 1];
            *(float2*)&out[(size_t)r0 * (2*C1) + coff + c] =
                make_float2(acc[m][j][0] + bv0, acc[m][j][1] + bv1);
            *(float2*)&out[(size_t)(r0 + 8) * (2*C1) + coff + c] =
                make_float2(acc[m][j][2] + bv0, acc[m][j][3] + bv1);
        }
    }
}

// ---------------- flash attention (round-14 version, stagger removed) ---------
// 3-stage ring of 128-key stages (two 64-key sub-tiles computed per stage),
// rotating producer, 16-row warps, 2 blocks/SM. QK^T f16 accum, ex2.f16x2
// in place, PV fp32 accum.
#define FA_OFF_Q   0                      // 128 rows x 128B = 16384
#define FA_OFF_KV  16384                  // stage s: K at +s*32768, V at +16384
#define FA_OFF_MB  114688                 // q(8) full[3](24) empty[3](24)
#define FA_SMEM    114752

__global__ __launch_bounds__(256, 2)
void flash_attn(const __half* __restrict__ Q1, const __half* __restrict__ KV1, __half* __restrict__ Y1,
                const __half* __restrict__ Q2, const __half* __restrict__ KV2, __half* __restrict__ Y2)
{
    extern __shared__ __align__(1024) char smem_raw[];
    const uint32_t sb = smem_u32(smem_raw);
    const uint32_t mbq = sb + FA_OFF_MB;
    const uint32_t mbf = mbq + 8;    // full[0..2]
    const uint32_t mbe = mbq + 32;   // empty[0..2]

    const int tid = threadIdx.x, lane = tid & 31, w = tid >> 5;
    const int q0 = blockIdx.x * 128;
    const int b = blockIdx.y / HH, h = blockIdx.y % HH;
    const bool br = blockIdx.z != 0;

    const __half* Q  = br ? Q2  : Q1;
    const __half* KV = br ? KV2 : KV1;
    __half*       Y  = br ? Y2  : Y1;

    const char* qplane = (const char*)Q  + ((size_t)b * HH + h) * ((size_t)NN * 128);
    const char* kplane = (const char*)KV + (((size_t)b * HH + h) * 2) * ((size_t)NN * 128);
    const char* vplane = kplane + (size_t)NN * 128;
    __half* Yb = Y + (size_t)b * NN * C1 + h * HD;

    const int nk2 = NN / 128;            // 32 stages of 128 keys

    if (tid == 0) {
        mbar_init(mbq, 1);
#pragma unroll
        for (int s = 0; s < 3; s++) {
            mbar_init(mbf + 8*s, 1);
            mbar_init(mbe + 8*s, 8);   // one arrival per warp
        }
    }
    __syncthreads();
    if (tid == 0) {
        mbar_expect(mbq, 16384);
        bulk_cp(sb + FA_OFF_Q, qplane + (size_t)q0 * 128, 16384, mbq);
#pragma unroll
        for (int s = 0; s < 3; s++) {
            mbar_expect(mbf + 8*s, 32768);
            bulk_cp(sb + FA_OFF_KV + s*32768,         kplane + (size_t)s * 16384, 16384, mbf + 8*s);
            bulk_cp(sb + FA_OFF_KV + s*32768 + 16384, vplane + (size_t)s * 16384, 16384, mbf + 8*s);
        }
    }

    // lane-constant swizzle XOR (row&7 == lane&7 for all fragment addresses)
    const int sxor = (lane & 7) << 4;

    // wait Q, pull persistent A fragments
    mbar_wait(mbq, 0);
    uint32_t aq[4][4];
    {
        const int qrow = 16*w + (lane & 15);
        const uint32_t qbase = sb + FA_OFF_Q + qrow * 128;
        const int qc = 16 * (lane >> 4);
#pragma unroll
        for (int ks = 0; ks < 4; ks++)
            ldm_x4(aq[ks][0], aq[ks][1], aq[ks][2], aq[ks][3], qbase + ((ks*32 + qc) ^ sxor));
    }

    float O[8][4];
#pragma unroll
    for (int j = 0; j < 8; j++)
#pragma unroll
        for (int x = 0; x < 4; x++) O[j][x] = 0.f;
    float lacc[2] = {0.f, 0.f};
    const __half2 hzero = __floats2half2_rn(0.f, 0.f);

    const int krow = ((lane >> 4) << 3) + (lane & 7);
    const int kc = 16 * ((lane >> 3) & 1);
    const int vrow = (((lane >> 3) & 1) << 3) + (lane & 7);
    const int vc = 16 * (lane >> 4);

    int st = 0, ph = 0;
    for (int kt = 0; kt < nk2; kt++) {
        mbar_wait(mbf + 8*st, ph);
        const uint32_t stage = sb + FA_OFF_KV + st * 32768;

#pragma unroll
        for (int sub = 0; sub < 2; sub++) {
            const uint32_t kbase = stage + sub * 8192;
            const uint32_t vbase = stage + 16384 + sub * 8192;

            // S = Q K^T, f16 accum
            uint32_t su[8][2];
#pragma unroll
            for (int n = 0; n < 8; n++) { su[n][0] = 0; su[n][1] = 0; }
#pragma unroll
            for (int ks = 0; ks < 4; ks++) {
#pragma unroll
                for (int jp = 0; jp < 4; jp++) {
                    uint32_t b0, b1, b2, b3;
                    ldm_x4(b0, b1, b2, b3, kbase + (16*jp + krow) * 128 + ((ks*32 + kc) ^ sxor));
                    mma16816h(su[2*jp][0],     su[2*jp][1],     aq[ks], b0, b1);
                    mma16816h(su[2*jp + 1][0], su[2*jp + 1][1], aq[ks], b2, b3);
                }
            }

            // p = 2^s in place, interleaved with PV mmas; l in half2 per subtile
            __half2 lh0 = hzero, lh1 = hzero;
#pragma unroll
            for (int ks = 0; ks < 4; ks++) {
                uint32_t pa[4];
                pa[0] = h2ex2(su[2*ks][0]);
                pa[1] = h2ex2(su[2*ks][1]);
                pa[2] = h2ex2(su[2*ks + 1][0]);
                pa[3] = h2ex2(su[2*ks + 1][1]);
                lh0 = __hadd2(lh0, __hadd2(u2h(pa[0]), u2h(pa[2])));
                lh1 = __hadd2(lh1, __hadd2(u2h(pa[1]), u2h(pa[3])));
#pragma unroll
                for (int dp = 0; dp < 4; dp++) {
                    uint32_t b0, b1, b2, b3;
                    ldm_x4_t(b0, b1, b2, b3, vbase + (ks*16 + vrow) * 128 + ((dp*32 + vc) ^ sxor));
                    mma16816(O[2*dp],     pa, b0, b1);
                    mma16816(O[2*dp + 1], pa, b2, b3);
                }
            }
            {
                float2 f0 = __half22float2(lh0);
                float2 f1 = __half22float2(lh1);
                lacc[0] += f0.x + f0.y;
                lacc[1] += f1.x + f1.y;
            }
        }

        // consumer release: this warp is done reading stage st
        if (lane == 0) mbar_arrive(mbe + 8*st);

        // rotating producer: warp (kt&7) refills stage st with tile kt+3
        if (w == (kt & 7) && lane == 0 && kt + 3 < nk2) {
            mbar_wait(mbe + 8*st, ph);
            mbar_expect(mbf + 8*st, 32768);
            bulk_cp(stage,         kplane + (size_t)(kt + 3) * 16384, 16384, mbf + 8*st);
            bulk_cp(stage + 16384, vplane + (size_t)(kt + 3) * 16384, 16384, mbf + 8*st);
        }

        if (++st == 3) { st = 0; ph ^= 1; }
    }

    // epilogue: reduce l across the 4 lanes of each row quad, scale, store
    float l0 = lacc[0], l1 = lacc[1];
    l0 += __shfl_xor_sync(0xffffffffu, l0, 1);
    l0 += __shfl_xor_sync(0xffffffffu, l0, 2);
    l1 += __shfl_xor_sync(0xffffffffu, l1, 1);
    l1 += __shfl_xor_sync(0xffffffffu, l1, 2);
    const float i0 = 1.f / l0, i1 = 1.f / l1;

    const int r0 = q0 + 16*w + (lane >> 2);
    const int cb = 2 * (lane & 3);
#pragma unroll
    for (int j = 0; j < 8; j++) {
        int c = cb + 8*j;
        *(__half2*)&Yb[(size_t)r0 * C1 + c]       = __floats2half2_rn(O[j][0] * i0, O[j][1] * i0);
        *(__half2*)&Yb[(size_t)(r0 + 8) * C1 + c] = __floats2half2_rn(O[j][2] * i1, O[j][3] * i1);
    }
}

// ---------------- launch ------------------------------------------------------
extern "C" void kernel_launch(void* const* d_in, const int* in_sizes, int n_in,
                              void* d_out, int out_size) {
    const float* x1  = (const float*)d_in[0];
    const float* x2  = (const float*)d_in[1];
    const float* q1w = (const float*)d_in[2];
    const float* q2w = (const float*)d_in[3];
    const float* kv1w = (const float*)d_in[4];
    const float* kv2w = (const float*)d_in[5];
    const float* p1w = (const float*)d_in[6];
    const float* p1b = (const float*)d_in[7];
    const float* p2w = (const float*)d_in[8];
    const float* p2b = (const float*)d_in[9];
    float* out = (float*)d_out;

    __half *x1h, *x2h, *wc1, *wc2, *wp1, *wp2, *q1, *q2, *kv1, *kv2, *y1, *y2;
    cudaGetSymbolAddress((void**)&x1h, g_x1h);
    cudaGetSymbolAddress((void**)&x2h, g_x2h);
    cudaGetSymbolAddress((void**)&wc1, g_wcat1);
    cudaGetSymbolAddress((void**)&wc2, g_wcat2);
    cudaGetSymbolAddress((void**)&wp1, g_wp1);
    cudaGetSymbolAddress((void**)&wp2, g_wp2);
    cudaGetSymbolAddress((void**)&q1, g_q1);
    cudaGetSymbolAddress((void**)&q2, g_q2);
    cudaGetSymbolAddress((void**)&kv1, g_kv1);
    cudaGetSymbolAddress((void**)&kv2, g_kv2);
    cudaGetSymbolAddress((void**)&y1, g_y1);
    cudaGetSymbolAddress((void**)&y2, g_y2);

    const int SMEM_G = 2 * (128 + 64) * 72 * 2;    // 55296 (2-stage, 4 blocks/SM)
    cudaFuncSetAttribute(flash_attn, cudaFuncAttributeMaxDynamicSharedMemorySize, FA_SMEM);
    cudaFuncSetAttribute(gemm_qkv,   cudaFuncAttributeMaxDynamicSharedMemorySize, SMEM_G);
    cudaFuncSetAttribute(gemm_proj,  cudaFuncAttributeMaxDynamicSharedMemorySize, SMEM_G);

    // fold HD^-0.5 AND log2(e) into q weights: S comes out in log2 units
    const float qscale = 0.125f * 1.44269504088896340736f;

    // merged conversion; q/kv weights land in concatenated buffers
    {
        ConvArgs a;
        const float* srcs[8] = {x1, x2, q1w, kv2w, q2w, kv1w, p1w, p2w};
        __half* dsts[8] = {x1h, x2h, wc1, wc1 + C1*C1, wc2, wc2 + C1*C2, wp1, wp2};
        int ns[8] = {MTOT*C1, MTOT*C2, C1*C1, 2*C1*C1, C1*C2, 2*C1*C2, C1*C1, C1*C1};
        float scs[8] = {1.f, 1.f, qscale, 1.f, qscale, 1.f, 1.f, 1.f};
        int cum = 0;
        for (int s = 0; s < 8; s++) {
            a.src[s] = (const float4*)srcs[s];
            a.dst[s] = (uint2*)dsts[s];
            a.scale[s] = scs[s];
            a.cum[s] = cum;
            cum += ns[s] / 4;
        }
        a.cum[8] = cum;
        f2h_multi<<<(cum + 255) / 256, 256>>>(a, cum);
    }

    // fused q+kv projections, both branches in one launch (z selects branch)
    gemm_qkv<<<dim3(3 * C1 / 64, MTOT / 128, 2), 128, SMEM_G>>>(
        x1h, wc1, q1, kv2, C1, x2h, wc2, q2, kv1, C2);

    // attention (both branches, one launch; 128 q-rows per block, 2 blocks/SM)
    flash_attn<<<dim3(NN / 128, BB * HH, 2), 256, FA_SMEM>>>(q1, kv1, y1, q2, kv2, y2);

    // output projections with bias (both branches), concat into out
    gemm_proj<<<dim3(C1 / 64, MTOT / 128, 2), 128, SMEM_G>>>(y1, wp1, y2, wp2, out, p1b, p2b);
}